// round 9
// baseline (speedup 1.0000x reference)
#include <cuda_runtime.h>

// Problem geometry (fixed by reference)
#define NCH    2560      // readout channels
#define NT     256       // ticks
#define NCHUNK 128       // 8B chunks (2 ticks) per channel row
#define NCELLS 40000     // cells per face
#define CAP    320       // max entries per output channel (even; Poisson(~100) safe)

// ---- static device scratch (no allocation allowed) ----
__device__ int     g_counts[NCH];           // zero-init at load; main_kernel re-zeroes
__device__ ushort2 g_entries[NCH * CAP];    // per-channel partner pairs, 3.3 MB
__device__ float   g_wf[8];                 // folded: w00,w10,w20,w01,w11,w21,be0,be1

typedef unsigned long long u64;

// Packed f32x2 FMA (sm_100+): d = a*b+c on both 32-bit halves. SASS: FFMA2.
__device__ __forceinline__ u64 fma2(u64 a, u64 b, u64 c) {
    u64 d;
    asm("fma.rn.f32x2 %0, %1, %2, %3;" : "=l"(d) : "l"(a), "l"(b), "l"(c));
    return d;
}
__device__ __forceinline__ float lo32(u64 v) { return __uint_as_float((unsigned)v); }
__device__ __forceinline__ float hi32(u64 v) { return __uint_as_float((unsigned)(v >> 32)); }
__device__ __forceinline__ u64 pack2(float a, float b) {
    return (u64)__float_as_uint(a) | ((u64)__float_as_uint(b) << 32);
}

// Read logical element i from an index table that may be int32 or int64
// (little-endian: lo word first; all values nonnegative < 2^31).
__device__ __forceinline__ int idx_ld(const int* p, int i, bool is64) {
    return is64 ? p[2 * i] : p[i];
}

#define PREP_BLOCKS  640                    // 640*256 threads, one float4 each = NCH*NT/4
#define BUILD_BLOCKS 313                    // ceil(80000/256)

// Fused pre-kernel: relu -> out plane0 (blocks [0,PREP)), bucket build
// (blocks [PREP, PREP+BUILD)), weight fold (last block). g_counts is zero
// (module init on run 1; main_kernel resets it every run).
__global__ void pre_kernel(const float* __restrict__ x, float* __restrict__ out,
                           const float* __restrict__ W1, const float* __restrict__ b1,
                           const float* __restrict__ W2, const float* __restrict__ b2,
                           const int* __restrict__ gi0, const int* __restrict__ gi1,
                           const int* __restrict__ wc00, const int* __restrict__ wc01,
                           const int* __restrict__ wc02, const int* __restrict__ wc10,
                           const int* __restrict__ wc11, const int* __restrict__ wc12) {
    int b = blockIdx.x, tid = threadIdx.x;
    if (b < PREP_BLOCKS) {
        int i = b * 256 + tid;                      // float4 index, < 163840
        float4 v = ((const float4*)x)[i];
        v.x = fmaxf(v.x, 0.f); v.y = fmaxf(v.y, 0.f);
        v.z = fmaxf(v.z, 0.f); v.w = fmaxf(v.w, 0.f);
        ((float4*)out)[i] = v;                      // plane 0 = relu(x); also main's gather src
        return;
    }
    if (b < PREP_BLOCKS + BUILD_BLOCKS) {
        int gid = (b - PREP_BLOCKS) * 256 + tid;
        if (gid >= 2 * NCELLS) return;
        // dtype sniff: int64 => these words are hi-halves (all 0). For int32
        // they are three distinct permutation channels (at most one can be 0).
        bool is64 = (wc00[1] == 0 && wc00[3] == 0 && wc00[5] == 0);
        int f = gid / NCELLS;
        int n = gid - f * NCELLS;
        const int* gi = f ? gi1 : gi0;
        const int* wa = f ? wc10 : wc00;
        const int* wb = f ? wc11 : wc01;
        const int* wd = f ? wc12 : wc02;

        int w0 = idx_ld(gi, n * 3 + 0, is64);
        int w1 = idx_ld(gi, n * 3 + 1, is64);
        int w2 = idx_ld(gi, n * 3 + 2, is64);
        int c0 = idx_ld(wa, w0 * 2 + 1, is64);      // plane 0, in [0,800)
        int c1 = idx_ld(wb, w1 * 2 + 1, is64);      // plane 1, in [800,1600)
        int c2 = idx_ld(wd, w2 * 2 + 1, is64);      // plane 2, in [1600,2560)

        // Bucket c stores the OTHER two channels (slot implied by c's range).
        int s0 = atomicAdd(&g_counts[c0], 1);
        if (s0 < CAP) g_entries[c0 * CAP + s0] =
            make_ushort2((unsigned short)c1, (unsigned short)c2);
        int s1 = atomicAdd(&g_counts[c1], 1);
        if (s1 < CAP) g_entries[c1 * CAP + s1] =
            make_ushort2((unsigned short)c0, (unsigned short)c2);
        int s2 = atomicAdd(&g_counts[c2], 1);
        if (s2 < CAP) g_entries[c2 * CAP + s2] =
            make_ushort2((unsigned short)c0, (unsigned short)c1);
        return;
    }
    // fold block: W1(3x8)@W2(8x2), beff = b1@W2 + b2
    if (tid == 0) {
        float s0 = b2[0], s1 = b2[1];
        float a[6] = {0.f, 0.f, 0.f, 0.f, 0.f, 0.f};
        #pragma unroll
        for (int h = 0; h < 8; ++h) {
            float v0 = W2[h * 2 + 0], v1 = W2[h * 2 + 1];
            s0 = fmaf(b1[h], v0, s0);
            s1 = fmaf(b1[h], v1, s1);
            #pragma unroll
            for (int r = 0; r < 3; ++r) {
                a[r]     = fmaf(W1[r * 8 + h], v0, a[r]);
                a[r + 3] = fmaf(W1[r * 8 + h], v1, a[r + 3]);
            }
        }
        #pragma unroll
        for (int r = 0; r < 6; ++r) g_wf[r] = a[r];
        g_wf[6] = s0; g_wf[7] = s1;
    }
}

// Main: one block per output channel; 128 threads, 2 ticks each (8B chunk).
// Self-row hoisted into a per-thread base; per entry per thread:
// 2x LDG.64 of partner chunks + 4 FFMA2 + 4 FMNMX. Gathers from out plane 0.
__global__ __launch_bounds__(128) void main_kernel(float* __restrict__ out) {
    int c   = blockIdx.x;
    int tid = threadIdx.x;   // 0..127 -> 8B chunk index within the row

    int slot = (c >= 800) + (c >= 1600);            // plane of channel c
    float ws0 = g_wf[slot],              ws1 = g_wf[3 + slot];
    float wa0 = g_wf[slot == 0 ? 1 : 0], wa1 = g_wf[slot == 0 ? 4 : 3];
    float wb0 = g_wf[slot == 2 ? 1 : 2], wb1 = g_wf[slot == 2 ? 4 : 5];
    float be0 = g_wf[6], be1 = g_wf[7];

    const u64* xr8 = (const u64*)out;               // plane 0 rows, 8B chunks
    u64 as = xr8[c * NCHUNK + tid];
    float sx = lo32(as), sy = hi32(as);
    // per-thread bases: self-plane contribution + bias (constant over entries)
    u64 base0 = pack2(fmaf(sx, ws0, be0), fmaf(sy, ws0, be0));
    u64 base1 = pack2(fmaf(sx, ws1, be1), fmaf(sy, ws1, be1));
    u64 wa0p = pack2(wa0, wa0), wb0p = pack2(wb0, wb0);
    u64 wa1p = pack2(wa1, wa1), wb1p = pack2(wb1, wb1);

    __shared__ ushort4 sE4[CAP / 2];
    ushort2* sE = (ushort2*)sE4;
    int cnt = min(g_counts[c], CAP);
    for (int i = tid; i < cnt; i += 128) sE[i] = g_entries[c * CAP + i];
    __syncthreads();
    if (tid == 0) g_counts[c] = 0;                  // reset for next replay

    float m0x = 0.f, m0y = 0.f, m1x = 0.f, m1y = 0.f;

    #define PROC(ea, eb)                                                       \
    {                                                                          \
        u64 A = xr8[(int)(ea) * NCHUNK + tid];                                 \
        u64 B = xr8[(int)(eb) * NCHUNK + tid];                                 \
        u64 t;                                                                 \
        t = fma2(A, wa0p, base0); t = fma2(B, wb0p, t);                        \
        m0x = fmaxf(m0x, lo32(t)); m0y = fmaxf(m0y, hi32(t));                  \
        t = fma2(A, wa1p, base1); t = fma2(B, wb1p, t);                        \
        m1x = fmaxf(m1x, lo32(t)); m1y = fmaxf(m1y, hi32(t));                  \
    }

    int npair = cnt >> 1;
    #pragma unroll 2
    for (int i = 0; i < npair; ++i) {
        ushort4 e2 = sE4[i];
        PROC(e2.x, e2.y);
        PROC(e2.z, e2.w);
    }
    if (cnt & 1) {
        ushort2 e = sE[cnt - 1];
        PROC(e.x, e.y);
    }
    #undef PROC

    // out layout (1, 3, NCH, NT): plane 0 written by pre_kernel.
    float2* o2 = (float2*)out;                      // 128 float2 per row
    o2[NCH * NCHUNK + c * NCHUNK + tid]     = make_float2(m0x, m0y);
    o2[2 * NCH * NCHUNK + c * NCHUNK + tid] = make_float2(m1x, m1y);
}

extern "C" void kernel_launch(void* const* d_in, const int* in_sizes, int n_in,
                              void* d_out, int out_size) {
    const float* x  = (const float*)d_in[0];
    const float* W1 = (const float*)d_in[1];
    const float* b1 = (const float*)d_in[2];
    const float* W2 = (const float*)d_in[3];
    const float* b2 = (const float*)d_in[4];
    const int* gi0  = (const int*)d_in[5];
    const int* gi1  = (const int*)d_in[6];
    const int* wc00 = (const int*)d_in[7];
    const int* wc01 = (const int*)d_in[8];
    const int* wc02 = (const int*)d_in[9];
    const int* wc10 = (const int*)d_in[10];
    const int* wc11 = (const int*)d_in[11];
    const int* wc12 = (const int*)d_in[12];

    pre_kernel<<<PREP_BLOCKS + BUILD_BLOCKS + 1, 256>>>(
        x, (float*)d_out, W1, b1, W2, b2,
        gi0, gi1, wc00, wc01, wc02, wc10, wc11, wc12);
    main_kernel<<<NCH, 128>>>((float*)d_out);
}

// round 11
// speedup vs baseline: 1.0845x; 1.0845x over previous
#include <cuda_runtime.h>

// Problem geometry (fixed by reference)
#define NCH    2560      // readout channels
#define NT     256       // ticks
#define NT16   64        // 16B chunks (ulonglong2) per row
#define NCELLS 40000     // cells per face
#define CAP    320       // max entries per output channel (even; Poisson(~100) safe)

// ---- static device scratch (no allocation allowed) ----
__device__ int     g_counts[NCH];           // zero-init at load; main_kernel re-zeroes
__device__ ushort2 g_entries[NCH * CAP];    // per-channel partner pairs, 3.3 MB
__device__ float   g_wf[8];                 // folded: w00,w10,w20,w01,w11,w21,be0,be1

typedef unsigned long long u64;

// Packed f32x2 FMA (sm_100+): d = a*b+c on both 32-bit halves. SASS: FFMA2.
__device__ __forceinline__ u64 fma2(u64 a, u64 b, u64 c) {
    u64 d;
    asm("fma.rn.f32x2 %0, %1, %2, %3;" : "=l"(d) : "l"(a), "l"(b), "l"(c));
    return d;
}
__device__ __forceinline__ float lo32(u64 v) { return __uint_as_float((unsigned)v); }
__device__ __forceinline__ float hi32(u64 v) { return __uint_as_float((unsigned)(v >> 32)); }
__device__ __forceinline__ u64 pack2(float a, float b) {
    return (u64)__float_as_uint(a) | ((u64)__float_as_uint(b) << 32);
}

// Read logical element i from an index table that may be int32 or int64
// (little-endian: lo word first; all values nonnegative < 2^31).
__device__ __forceinline__ int idx_ld(const int* p, int i, bool is64) {
    return is64 ? p[2 * i] : p[i];
}

#define PREP_BLOCKS  640                    // 640*256 threads, one float4 each = NCH*NT/4
#define BUILD_BLOCKS 313                    // ceil(80000/256)

// Fused pre-kernel: relu -> out plane0 (blocks [0,PREP)), bucket build
// (blocks [PREP, PREP+BUILD)), weight fold (last block). g_counts is zero
// (module init on run 1; main_kernel resets it every run).
__global__ void pre_kernel(const float* __restrict__ x, float* __restrict__ out,
                           const float* __restrict__ W1, const float* __restrict__ b1,
                           const float* __restrict__ W2, const float* __restrict__ b2,
                           const int* __restrict__ gi0, const int* __restrict__ gi1,
                           const int* __restrict__ wc00, const int* __restrict__ wc01,
                           const int* __restrict__ wc02, const int* __restrict__ wc10,
                           const int* __restrict__ wc11, const int* __restrict__ wc12) {
    int b = blockIdx.x, tid = threadIdx.x;
    if (b < PREP_BLOCKS) {
        int i = b * 256 + tid;                      // float4 index, < 163840
        float4 v = ((const float4*)x)[i];
        v.x = fmaxf(v.x, 0.f); v.y = fmaxf(v.y, 0.f);
        v.z = fmaxf(v.z, 0.f); v.w = fmaxf(v.w, 0.f);
        ((float4*)out)[i] = v;                      // plane 0 = relu(x); also main's gather src
        return;
    }
    if (b < PREP_BLOCKS + BUILD_BLOCKS) {
        int gid = (b - PREP_BLOCKS) * 256 + tid;
        if (gid >= 2 * NCELLS) return;
        // dtype sniff: int64 => these words are hi-halves (all 0). For int32
        // they are three distinct permutation channels (at most one can be 0).
        bool is64 = (wc00[1] == 0 && wc00[3] == 0 && wc00[5] == 0);
        int f = gid / NCELLS;
        int n = gid - f * NCELLS;
        const int* gi = f ? gi1 : gi0;
        const int* wa = f ? wc10 : wc00;
        const int* wb = f ? wc11 : wc01;
        const int* wd = f ? wc12 : wc02;

        int w0 = idx_ld(gi, n * 3 + 0, is64);
        int w1 = idx_ld(gi, n * 3 + 1, is64);
        int w2 = idx_ld(gi, n * 3 + 2, is64);
        int c0 = idx_ld(wa, w0 * 2 + 1, is64);      // plane 0, in [0,800)
        int c1 = idx_ld(wb, w1 * 2 + 1, is64);      // plane 1, in [800,1600)
        int c2 = idx_ld(wd, w2 * 2 + 1, is64);      // plane 2, in [1600,2560)

        // Bucket c stores the OTHER two channels (slot implied by c's range).
        int s0 = atomicAdd(&g_counts[c0], 1);
        if (s0 < CAP) g_entries[c0 * CAP + s0] =
            make_ushort2((unsigned short)c1, (unsigned short)c2);
        int s1 = atomicAdd(&g_counts[c1], 1);
        if (s1 < CAP) g_entries[c1 * CAP + s1] =
            make_ushort2((unsigned short)c0, (unsigned short)c2);
        int s2 = atomicAdd(&g_counts[c2], 1);
        if (s2 < CAP) g_entries[c2 * CAP + s2] =
            make_ushort2((unsigned short)c0, (unsigned short)c1);
        return;
    }
    // fold block: W1(3x8)@W2(8x2), beff = b1@W2 + b2
    if (tid == 0) {
        float s0 = b2[0], s1 = b2[1];
        float a[6] = {0.f, 0.f, 0.f, 0.f, 0.f, 0.f};
        #pragma unroll
        for (int h = 0; h < 8; ++h) {
            float v0 = W2[h * 2 + 0], v1 = W2[h * 2 + 1];
            s0 = fmaf(b1[h], v0, s0);
            s1 = fmaf(b1[h], v1, s1);
            #pragma unroll
            for (int r = 0; r < 3; ++r) {
                a[r]     = fmaf(W1[r * 8 + h], v0, a[r]);
                a[r + 3] = fmaf(W1[r * 8 + h], v1, a[r + 3]);
            }
        }
        #pragma unroll
        for (int r = 0; r < 6; ++r) g_wf[r] = a[r];
        g_wf[6] = s0; g_wf[7] = s1;
    }
}

// Main: one block per output channel; 64 threads, 4 ticks each (16B, LDG.128).
// Self-row hoisted into per-thread bases; per entry: 2x LDG.128 of partner
// rows + 8 FFMA2 + 8 FMNMX. Explicit software pipeline: entry i+1's rows are
// loaded while entry i computes, to raise outstanding-load count (latency
// was the R8 binding constraint; LDG.128 retained per R9 LSU lesson).
__global__ __launch_bounds__(64) void main_kernel(float* __restrict__ out) {
    int c   = blockIdx.x;
    int tid = threadIdx.x;   // 0..63

    int slot = (c >= 800) + (c >= 1600);            // plane of channel c
    float ws0 = g_wf[slot],              ws1 = g_wf[3 + slot];
    float wa0 = g_wf[slot == 0 ? 1 : 0], wa1 = g_wf[slot == 0 ? 4 : 3];
    float wb0 = g_wf[slot == 2 ? 1 : 2], wb1 = g_wf[slot == 2 ? 4 : 5];
    float be0 = g_wf[6], be1 = g_wf[7];

    const ulonglong2* xr8 = (const ulonglong2*)out;   // plane 0 rows, 16B chunks
    ulonglong2 as = xr8[c * NT16 + tid];
    float sx = lo32(as.x), sy = hi32(as.x), sz = lo32(as.y), sw = hi32(as.y);
    // per-thread bases: self-plane contribution + bias (constant over entries)
    u64 base0lo = pack2(fmaf(sx, ws0, be0), fmaf(sy, ws0, be0));
    u64 base0hi = pack2(fmaf(sz, ws0, be0), fmaf(sw, ws0, be0));
    u64 base1lo = pack2(fmaf(sx, ws1, be1), fmaf(sy, ws1, be1));
    u64 base1hi = pack2(fmaf(sz, ws1, be1), fmaf(sw, ws1, be1));
    u64 wa0p = pack2(wa0, wa0), wb0p = pack2(wb0, wb0);
    u64 wa1p = pack2(wa1, wa1), wb1p = pack2(wb1, wb1);

    __shared__ ushort2 sE[CAP];
    int cnt = min(g_counts[c], CAP);
    for (int i = tid; i < cnt; i += 64) sE[i] = g_entries[c * CAP + i];
    __syncthreads();
    if (tid == 0) g_counts[c] = 0;                  // reset for next replay

    float m0x = 0.f, m0y = 0.f, m0z = 0.f, m0w = 0.f;
    float m1x = 0.f, m1y = 0.f, m1z = 0.f, m1w = 0.f;

    #define COMPUTE(A, B)                                                      \
    {                                                                          \
        u64 t;                                                                 \
        t = fma2((A).x, wa0p, base0lo); t = fma2((B).x, wb0p, t);              \
        m0x = fmaxf(m0x, lo32(t));      m0y = fmaxf(m0y, hi32(t));             \
        t = fma2((A).y, wa0p, base0hi); t = fma2((B).y, wb0p, t);              \
        m0z = fmaxf(m0z, lo32(t));      m0w = fmaxf(m0w, hi32(t));             \
        t = fma2((A).x, wa1p, base1lo); t = fma2((B).x, wb1p, t);              \
        m1x = fmaxf(m1x, lo32(t));      m1y = fmaxf(m1y, hi32(t));             \
        t = fma2((A).y, wa1p, base1hi); t = fma2((B).y, wb1p, t);              \
        m1z = fmaxf(m1z, lo32(t));      m1w = fmaxf(m1w, hi32(t));             \
    }

    if (cnt > 0) {
        ushort2 e0 = sE[0];
        ulonglong2 A = xr8[(int)e0.x * NT16 + tid];
        ulonglong2 B = xr8[(int)e0.y * NT16 + tid];
        #pragma unroll 2
        for (int i = 1; i < cnt; ++i) {
            ushort2 en = sE[i];
            ulonglong2 An = xr8[(int)en.x * NT16 + tid];
            ulonglong2 Bn = xr8[(int)en.y * NT16 + tid];
            COMPUTE(A, B);
            A = An; B = Bn;
        }
        COMPUTE(A, B);
    }
    #undef COMPUTE

    // out layout (1, 3, NCH, NT): plane 0 written by pre_kernel.
    float4* o4 = (float4*)out;
    int nt4 = NT / 4;
    o4[NCH * nt4 + c * nt4 + tid]     = make_float4(m0x, m0y, m0z, m0w);
    o4[2 * NCH * nt4 + c * nt4 + tid] = make_float4(m1x, m1y, m1z, m1w);
}

extern "C" void kernel_launch(void* const* d_in, const int* in_sizes, int n_in,
                              void* d_out, int out_size) {
    const float* x  = (const float*)d_in[0];
    const float* W1 = (const float*)d_in[1];
    const float* b1 = (const float*)d_in[2];
    const float* W2 = (const float*)d_in[3];
    const float* b2 = (const float*)d_in[4];
    const int* gi0  = (const int*)d_in[5];
    const int* gi1  = (const int*)d_in[6];
    const int* wc00 = (const int*)d_in[7];
    const int* wc01 = (const int*)d_in[8];
    const int* wc02 = (const int*)d_in[9];
    const int* wc10 = (const int*)d_in[10];
    const int* wc11 = (const int*)d_in[11];
    const int* wc12 = (const int*)d_in[12];

    pre_kernel<<<PREP_BLOCKS + BUILD_BLOCKS + 1, 256>>>(
        x, (float*)d_out, W1, b1, W2, b2,
        gi0, gi1, wc00, wc01, wc02, wc10, wc11, wc12);
    main_kernel<<<NCH, 64>>>((float*)d_out);
}

// round 12
// speedup vs baseline: 1.1200x; 1.0327x over previous
#include <cuda_runtime.h>

// Problem geometry (fixed by reference)
#define NCH    2560      // readout channels
#define NT     256       // ticks
#define NT16   64        // 16B chunks (ulonglong2) per row
#define NCELLS 40000     // cells per face
#define CAP    320       // max entries per output channel (even; Poisson(~100) safe)

// ---- static device scratch (no allocation allowed) ----
__device__ int     g_counts[NCH];           // zero-init at load; main_kernel re-zeroes
__device__ ushort2 g_entries[NCH * CAP];    // per-channel partner pairs, 3.3 MB
__device__ float   g_wf[8];                 // folded: w00,w10,w20,w01,w11,w21,be0,be1

typedef unsigned long long u64;

// Packed f32x2 FMA (sm_100+): d = a*b+c on both 32-bit halves. SASS: FFMA2.
__device__ __forceinline__ u64 fma2(u64 a, u64 b, u64 c) {
    u64 d;
    asm("fma.rn.f32x2 %0, %1, %2, %3;" : "=l"(d) : "l"(a), "l"(b), "l"(c));
    return d;
}
__device__ __forceinline__ float lo32(u64 v) { return __uint_as_float((unsigned)v); }
__device__ __forceinline__ float hi32(u64 v) { return __uint_as_float((unsigned)(v >> 32)); }
__device__ __forceinline__ u64 pack2(float a, float b) {
    return (u64)__float_as_uint(a) | ((u64)__float_as_uint(b) << 32);
}

// Read logical element i from an index table that may be int32 or int64
// (little-endian: lo word first; all values nonnegative < 2^31).
__device__ __forceinline__ int idx_ld(const int* p, int i, bool is64) {
    return is64 ? p[2 * i] : p[i];
}

#define PREP_BLOCKS  640                    // 640*256 threads, one float4 each = NCH*NT/4
#define BUILD_BLOCKS 313                    // ceil(80000/256)

// Fused pre-kernel: relu -> out plane0 (blocks [0,PREP)), bucket build
// (blocks [PREP, PREP+BUILD)), weight fold (last block). g_counts is zero
// (module init on run 1; main_kernel resets it every run).
__global__ void pre_kernel(const float* __restrict__ x, float* __restrict__ out,
                           const float* __restrict__ W1, const float* __restrict__ b1,
                           const float* __restrict__ W2, const float* __restrict__ b2,
                           const int* __restrict__ gi0, const int* __restrict__ gi1,
                           const int* __restrict__ wc00, const int* __restrict__ wc01,
                           const int* __restrict__ wc02, const int* __restrict__ wc10,
                           const int* __restrict__ wc11, const int* __restrict__ wc12) {
    int b = blockIdx.x, tid = threadIdx.x;
    if (b < PREP_BLOCKS) {
        int i = b * 256 + tid;                      // float4 index, < 163840
        float4 v = ((const float4*)x)[i];
        v.x = fmaxf(v.x, 0.f); v.y = fmaxf(v.y, 0.f);
        v.z = fmaxf(v.z, 0.f); v.w = fmaxf(v.w, 0.f);
        ((float4*)out)[i] = v;                      // plane 0 = relu(x); also main's gather src
        return;
    }
    if (b < PREP_BLOCKS + BUILD_BLOCKS) {
        int gid = (b - PREP_BLOCKS) * 256 + tid;
        if (gid >= 2 * NCELLS) return;
        // dtype sniff: int64 => these words are hi-halves (all 0). For int32
        // they are three distinct permutation channels (at most one can be 0).
        bool is64 = (wc00[1] == 0 && wc00[3] == 0 && wc00[5] == 0);
        int f = gid / NCELLS;
        int n = gid - f * NCELLS;
        const int* gi = f ? gi1 : gi0;
        const int* wa = f ? wc10 : wc00;
        const int* wb = f ? wc11 : wc01;
        const int* wd = f ? wc12 : wc02;

        int w0 = idx_ld(gi, n * 3 + 0, is64);
        int w1 = idx_ld(gi, n * 3 + 1, is64);
        int w2 = idx_ld(gi, n * 3 + 2, is64);
        int c0 = idx_ld(wa, w0 * 2 + 1, is64);      // plane 0, in [0,800)
        int c1 = idx_ld(wb, w1 * 2 + 1, is64);      // plane 1, in [800,1600)
        int c2 = idx_ld(wd, w2 * 2 + 1, is64);      // plane 2, in [1600,2560)

        // Bucket c stores the OTHER two channels (slot implied by c's range).
        int s0 = atomicAdd(&g_counts[c0], 1);
        if (s0 < CAP) g_entries[c0 * CAP + s0] =
            make_ushort2((unsigned short)c1, (unsigned short)c2);
        int s1 = atomicAdd(&g_counts[c1], 1);
        if (s1 < CAP) g_entries[c1 * CAP + s1] =
            make_ushort2((unsigned short)c0, (unsigned short)c2);
        int s2 = atomicAdd(&g_counts[c2], 1);
        if (s2 < CAP) g_entries[c2 * CAP + s2] =
            make_ushort2((unsigned short)c0, (unsigned short)c1);
        return;
    }
    // fold block: W1(3x8)@W2(8x2), beff = b1@W2 + b2
    if (tid == 0) {
        float s0 = b2[0], s1 = b2[1];
        float a[6] = {0.f, 0.f, 0.f, 0.f, 0.f, 0.f};
        #pragma unroll
        for (int h = 0; h < 8; ++h) {
            float v0 = W2[h * 2 + 0], v1 = W2[h * 2 + 1];
            s0 = fmaf(b1[h], v0, s0);
            s1 = fmaf(b1[h], v1, s1);
            #pragma unroll
            for (int r = 0; r < 3; ++r) {
                a[r]     = fmaf(W1[r * 8 + h], v0, a[r]);
                a[r + 3] = fmaf(W1[r * 8 + h], v1, a[r + 3]);
            }
        }
        #pragma unroll
        for (int r = 0; r < 6; ++r) g_wf[r] = a[r];
        g_wf[6] = s0; g_wf[7] = s1;
    }
}

// Main: one block per output channel; 128 threads = 2 entry-halves x 64 tick
// threads (16B LDG.128 each). Per-entry body identical to the proven R8 form
// (compiler-scheduled, unroll 4); halves merge via smem max at the end.
// Doubles resident warps/SM for latency hiding without shrinking load width.
__global__ __launch_bounds__(128) void main_kernel(float* __restrict__ out) {
    int c   = blockIdx.x;
    int tid = threadIdx.x;   // 0..127
    int h   = tid >> 6;      // entry-half index (0 or 1)
    int t   = tid & 63;      // 16B tick-chunk index

    int slot = (c >= 800) + (c >= 1600);            // plane of channel c
    float ws0 = g_wf[slot],              ws1 = g_wf[3 + slot];
    float wa0 = g_wf[slot == 0 ? 1 : 0], wa1 = g_wf[slot == 0 ? 4 : 3];
    float wb0 = g_wf[slot == 2 ? 1 : 2], wb1 = g_wf[slot == 2 ? 4 : 5];
    float be0 = g_wf[6], be1 = g_wf[7];

    const ulonglong2* xr8 = (const ulonglong2*)out;   // plane 0 rows, 16B chunks
    ulonglong2 as = xr8[c * NT16 + t];
    float sx = lo32(as.x), sy = hi32(as.x), sz = lo32(as.y), sw = hi32(as.y);
    // per-thread bases: self-plane contribution + bias (constant over entries)
    u64 base0lo = pack2(fmaf(sx, ws0, be0), fmaf(sy, ws0, be0));
    u64 base0hi = pack2(fmaf(sz, ws0, be0), fmaf(sw, ws0, be0));
    u64 base1lo = pack2(fmaf(sx, ws1, be1), fmaf(sy, ws1, be1));
    u64 base1hi = pack2(fmaf(sz, ws1, be1), fmaf(sw, ws1, be1));
    u64 wa0p = pack2(wa0, wa0), wb0p = pack2(wb0, wb0);
    u64 wa1p = pack2(wa1, wa1), wb1p = pack2(wb1, wb1);

    __shared__ ushort2 sE[CAP];
    __shared__ float   sM[8][64];
    int cnt = min(g_counts[c], CAP);
    for (int i = tid; i < cnt; i += 128) sE[i] = g_entries[c * CAP + i];
    __syncthreads();
    if (tid == 0) g_counts[c] = 0;                  // reset for next replay

    float m0x = 0.f, m0y = 0.f, m0z = 0.f, m0w = 0.f;
    float m1x = 0.f, m1y = 0.f, m1z = 0.f, m1w = 0.f;

    int s = h ? (cnt >> 1) : 0;
    int e = h ? cnt : (cnt >> 1);
    #pragma unroll 4
    for (int i = s; i < e; ++i) {
        ushort2 en = sE[i];
        ulonglong2 A = xr8[(int)en.x * NT16 + t];
        ulonglong2 B = xr8[(int)en.y * NT16 + t];
        u64 tt;
        tt = fma2(A.x, wa0p, base0lo); tt = fma2(B.x, wb0p, tt);
        m0x = fmaxf(m0x, lo32(tt));    m0y = fmaxf(m0y, hi32(tt));
        tt = fma2(A.y, wa0p, base0hi); tt = fma2(B.y, wb0p, tt);
        m0z = fmaxf(m0z, lo32(tt));    m0w = fmaxf(m0w, hi32(tt));
        tt = fma2(A.x, wa1p, base1lo); tt = fma2(B.x, wb1p, tt);
        m1x = fmaxf(m1x, lo32(tt));    m1y = fmaxf(m1y, hi32(tt));
        tt = fma2(A.y, wa1p, base1hi); tt = fma2(B.y, wb1p, tt);
        m1z = fmaxf(m1z, lo32(tt));    m1w = fmaxf(m1w, hi32(tt));
    }

    // Merge halves: half 1 publishes, half 0 reduces and stores.
    if (h == 1) {
        sM[0][t] = m0x; sM[1][t] = m0y; sM[2][t] = m0z; sM[3][t] = m0w;
        sM[4][t] = m1x; sM[5][t] = m1y; sM[6][t] = m1z; sM[7][t] = m1w;
    }
    __syncthreads();
    if (h == 0) {
        m0x = fmaxf(m0x, sM[0][t]); m0y = fmaxf(m0y, sM[1][t]);
        m0z = fmaxf(m0z, sM[2][t]); m0w = fmaxf(m0w, sM[3][t]);
        m1x = fmaxf(m1x, sM[4][t]); m1y = fmaxf(m1y, sM[5][t]);
        m1z = fmaxf(m1z, sM[6][t]); m1w = fmaxf(m1w, sM[7][t]);

        // out layout (1, 3, NCH, NT): plane 0 written by pre_kernel.
        float4* o4 = (float4*)out;
        int nt4 = NT / 4;
        o4[NCH * nt4 + c * nt4 + t]     = make_float4(m0x, m0y, m0z, m0w);
        o4[2 * NCH * nt4 + c * nt4 + t] = make_float4(m1x, m1y, m1z, m1w);
    }
}

extern "C" void kernel_launch(void* const* d_in, const int* in_sizes, int n_in,
                              void* d_out, int out_size) {
    const float* x  = (const float*)d_in[0];
    const float* W1 = (const float*)d_in[1];
    const float* b1 = (const float*)d_in[2];
    const float* W2 = (const float*)d_in[3];
    const float* b2 = (const float*)d_in[4];
    const int* gi0  = (const int*)d_in[5];
    const int* gi1  = (const int*)d_in[6];
    const int* wc00 = (const int*)d_in[7];
    const int* wc01 = (const int*)d_in[8];
    const int* wc02 = (const int*)d_in[9];
    const int* wc10 = (const int*)d_in[10];
    const int* wc11 = (const int*)d_in[11];
    const int* wc12 = (const int*)d_in[12];

    pre_kernel<<<PREP_BLOCKS + BUILD_BLOCKS + 1, 256>>>(
        x, (float*)d_out, W1, b1, W2, b2,
        gi0, gi1, wc00, wc01, wc02, wc10, wc11, wc12);
    main_kernel<<<NCH, 128>>>((float*)d_out);
}

// round 13
// speedup vs baseline: 1.2297x; 1.0980x over previous
#include <cuda_runtime.h>

// Problem geometry (fixed by reference)
#define NCH    2560      // readout channels
#define NT     256       // ticks
#define NT16   64        // 16B chunks (ulonglong2) per row
#define NCELLS 40000     // cells per face
#define NSUB   4         // sub-buckets per channel (atomic-contention spread)
#define SUBCAP 96        // capacity per sub-bucket (expected ~24; 4x margin)
#define CAPTOT (NSUB * SUBCAP)   // 384 max entries per channel

// ---- static device scratch (no allocation allowed) ----
__device__ int     g_counts[NCH * NSUB];        // zero-init; main re-zeroes
__device__ ushort2 g_entries[NCH * CAPTOT];     // per-channel partner pairs
__device__ float   g_wf[8];                     // folded weights + bias

typedef unsigned long long u64;

// Packed f32x2 FMA (sm_100+): d = a*b+c on both 32-bit halves. SASS: FFMA2.
__device__ __forceinline__ u64 fma2(u64 a, u64 b, u64 c) {
    u64 d;
    asm("fma.rn.f32x2 %0, %1, %2, %3;" : "=l"(d) : "l"(a), "l"(b), "l"(c));
    return d;
}
__device__ __forceinline__ float lo32(u64 v) { return __uint_as_float((unsigned)v); }
__device__ __forceinline__ float hi32(u64 v) { return __uint_as_float((unsigned)(v >> 32)); }
__device__ __forceinline__ u64 pack2(float a, float b) {
    return (u64)__float_as_uint(a) | ((u64)__float_as_uint(b) << 32);
}

// Read logical element i from an index table that may be int32 or int64
// (little-endian: lo word first; all values nonnegative < 2^31).
__device__ __forceinline__ int idx_ld(const int* p, int i, bool is64) {
    return is64 ? p[2 * i] : p[i];
}

#define PREP_BLOCKS  640                    // 640*256 threads, one float4 each = NCH*NT/4
#define BUILD_BLOCKS 313                    // ceil(80000/256)

// Fused pre-kernel: relu -> out plane0 (blocks [0,PREP)), bucket build
// (blocks [PREP, PREP+BUILD)), weight fold (last block). g_counts is zero
// (module init on run 1; main_kernel resets it every run).
__global__ void pre_kernel(const float* __restrict__ x, float* __restrict__ out,
                           const float* __restrict__ W1, const float* __restrict__ b1,
                           const float* __restrict__ W2, const float* __restrict__ b2,
                           const int* __restrict__ gi0, const int* __restrict__ gi1,
                           const int* __restrict__ wc00, const int* __restrict__ wc01,
                           const int* __restrict__ wc02, const int* __restrict__ wc10,
                           const int* __restrict__ wc11, const int* __restrict__ wc12) {
    int b = blockIdx.x, tid = threadIdx.x;
    if (b < PREP_BLOCKS) {
        int i = b * 256 + tid;                      // float4 index, < 163840
        float4 v = ((const float4*)x)[i];
        v.x = fmaxf(v.x, 0.f); v.y = fmaxf(v.y, 0.f);
        v.z = fmaxf(v.z, 0.f); v.w = fmaxf(v.w, 0.f);
        ((float4*)out)[i] = v;                      // plane 0 = relu(x); also main's gather src
        return;
    }
    if (b < PREP_BLOCKS + BUILD_BLOCKS) {
        int gid = (b - PREP_BLOCKS) * 256 + tid;
        if (gid >= 2 * NCELLS) return;
        // dtype sniff: int64 => these words are hi-halves (all 0). For int32
        // they are three distinct permutation channels (at most one can be 0).
        bool is64 = (wc00[1] == 0 && wc00[3] == 0 && wc00[5] == 0);
        int f = gid / NCELLS;
        int n = gid - f * NCELLS;
        const int* gi = f ? gi1 : gi0;
        const int* wa = f ? wc10 : wc00;
        const int* wb = f ? wc11 : wc01;
        const int* wd = f ? wc12 : wc02;

        int w0 = idx_ld(gi, n * 3 + 0, is64);
        int w1 = idx_ld(gi, n * 3 + 1, is64);
        int w2 = idx_ld(gi, n * 3 + 2, is64);
        int c0 = idx_ld(wa, w0 * 2 + 1, is64);      // plane 0, in [0,800)
        int c1 = idx_ld(wb, w1 * 2 + 1, is64);      // plane 1, in [800,1600)
        int c2 = idx_ld(wd, w2 * 2 + 1, is64);      // plane 2, in [1600,2560)

        // Bucket c stores the OTHER two channels (slot implied by c's range).
        // Sub-bucket (gid&3) spreads atomic contention 4x per channel.
        int sub = gid & (NSUB - 1);
        int s0 = atomicAdd(&g_counts[c0 * NSUB + sub], 1);
        if (s0 < SUBCAP) g_entries[c0 * CAPTOT + sub * SUBCAP + s0] =
            make_ushort2((unsigned short)c1, (unsigned short)c2);
        int s1 = atomicAdd(&g_counts[c1 * NSUB + sub], 1);
        if (s1 < SUBCAP) g_entries[c1 * CAPTOT + sub * SUBCAP + s1] =
            make_ushort2((unsigned short)c0, (unsigned short)c2);
        int s2 = atomicAdd(&g_counts[c2 * NSUB + sub], 1);
        if (s2 < SUBCAP) g_entries[c2 * CAPTOT + sub * SUBCAP + s2] =
            make_ushort2((unsigned short)c0, (unsigned short)c1);
        return;
    }
    // fold block: W1(3x8)@W2(8x2), beff = b1@W2 + b2
    if (tid == 0) {
        float s0 = b2[0], s1 = b2[1];
        float a[6] = {0.f, 0.f, 0.f, 0.f, 0.f, 0.f};
        #pragma unroll
        for (int h = 0; h < 8; ++h) {
            float v0 = W2[h * 2 + 0], v1 = W2[h * 2 + 1];
            s0 = fmaf(b1[h], v0, s0);
            s1 = fmaf(b1[h], v1, s1);
            #pragma unroll
            for (int r = 0; r < 3; ++r) {
                a[r]     = fmaf(W1[r * 8 + h], v0, a[r]);
                a[r + 3] = fmaf(W1[r * 8 + h], v1, a[r + 3]);
            }
        }
        #pragma unroll
        for (int r = 0; r < 6; ++r) g_wf[r] = a[r];
        g_wf[6] = s0; g_wf[7] = s1;
    }
}

// Main: one block per output channel; 64 threads, 4 ticks each (16B, LDG.128).
// Hot loop is the proven R8 form (compiler-scheduled, ushort4-paired, unroll 2).
// Prologue concatenates the 4 sub-bucket segments into contiguous smem.
__global__ __launch_bounds__(64) void main_kernel(float* __restrict__ out) {
    int c   = blockIdx.x;
    int tid = threadIdx.x;   // 0..63

    int slot = (c >= 800) + (c >= 1600);            // plane of channel c
    float ws0 = g_wf[slot],              ws1 = g_wf[3 + slot];
    float wa0 = g_wf[slot == 0 ? 1 : 0], wa1 = g_wf[slot == 0 ? 4 : 3];
    float wb0 = g_wf[slot == 2 ? 1 : 2], wb1 = g_wf[slot == 2 ? 4 : 5];
    float be0 = g_wf[6], be1 = g_wf[7];

    const ulonglong2* xr8 = (const ulonglong2*)out;   // plane 0 rows, 16B chunks
    ulonglong2 as = xr8[c * NT16 + tid];
    float sx = lo32(as.x), sy = hi32(as.x), sz = lo32(as.y), sw = hi32(as.y);
    // per-thread bases: self-plane contribution + bias (constant over entries)
    u64 base0lo = pack2(fmaf(sx, ws0, be0), fmaf(sy, ws0, be0));
    u64 base0hi = pack2(fmaf(sz, ws0, be0), fmaf(sw, ws0, be0));
    u64 base1lo = pack2(fmaf(sx, ws1, be1), fmaf(sy, ws1, be1));
    u64 base1hi = pack2(fmaf(sz, ws1, be1), fmaf(sw, ws1, be1));
    u64 wa0p = pack2(wa0, wa0), wb0p = pack2(wb0, wb0);
    u64 wa1p = pack2(wa1, wa1), wb1p = pack2(wb1, wb1);

    __shared__ ushort4 sE4[CAPTOT / 2];
    ushort2* sE = (ushort2*)sE4;
    // Concatenate 4 sub-bucket segments into contiguous sE[0..cnt).
    int cs[NSUB], off[NSUB], cnt = 0;
    #pragma unroll
    for (int s = 0; s < NSUB; ++s) {
        cs[s]  = min(g_counts[c * NSUB + s], SUBCAP);
        off[s] = cnt;
        cnt   += cs[s];
    }
    #pragma unroll
    for (int s = 0; s < NSUB; ++s)
        for (int i = tid; i < cs[s]; i += 64)
            sE[off[s] + i] = g_entries[c * CAPTOT + s * SUBCAP + i];
    __syncthreads();
    if (tid < NSUB) g_counts[c * NSUB + tid] = 0;   // reset for next replay

    float m0x = 0.f, m0y = 0.f, m0z = 0.f, m0w = 0.f;
    float m1x = 0.f, m1y = 0.f, m1z = 0.f, m1w = 0.f;

    #define PROC(ea, eb)                                                       \
    {                                                                          \
        ulonglong2 A = xr8[(int)(ea) * NT16 + tid];                            \
        ulonglong2 B = xr8[(int)(eb) * NT16 + tid];                            \
        u64 t;                                                                 \
        t = fma2(A.x, wa0p, base0lo); t = fma2(B.x, wb0p, t);                  \
        m0x = fmaxf(m0x, lo32(t));    m0y = fmaxf(m0y, hi32(t));               \
        t = fma2(A.y, wa0p, base0hi); t = fma2(B.y, wb0p, t);                  \
        m0z = fmaxf(m0z, lo32(t));    m0w = fmaxf(m0w, hi32(t));               \
        t = fma2(A.x, wa1p, base1lo); t = fma2(B.x, wb1p, t);                  \
        m1x = fmaxf(m1x, lo32(t));    m1y = fmaxf(m1y, hi32(t));               \
        t = fma2(A.y, wa1p, base1hi); t = fma2(B.y, wb1p, t);                  \
        m1z = fmaxf(m1z, lo32(t));    m1w = fmaxf(m1w, hi32(t));               \
    }

    int npair = cnt >> 1;
    #pragma unroll 2
    for (int i = 0; i < npair; ++i) {
        ushort4 e2 = sE4[i];
        PROC(e2.x, e2.y);
        PROC(e2.z, e2.w);
    }
    if (cnt & 1) {
        ushort2 e = sE[cnt - 1];
        PROC(e.x, e.y);
    }
    #undef PROC

    // out layout (1, 3, NCH, NT): plane 0 written by pre_kernel.
    float4* o4 = (float4*)out;
    int nt4 = NT / 4;
    o4[NCH * nt4 + c * nt4 + tid]     = make_float4(m0x, m0y, m0z, m0w);
    o4[2 * NCH * nt4 + c * nt4 + tid] = make_float4(m1x, m1y, m1z, m1w);
}

extern "C" void kernel_launch(void* const* d_in, const int* in_sizes, int n_in,
                              void* d_out, int out_size) {
    const float* x  = (const float*)d_in[0];
    const float* W1 = (const float*)d_in[1];
    const float* b1 = (const float*)d_in[2];
    const float* W2 = (const float*)d_in[3];
    const float* b2 = (const float*)d_in[4];
    const int* gi0  = (const int*)d_in[5];
    const int* gi1  = (const int*)d_in[6];
    const int* wc00 = (const int*)d_in[7];
    const int* wc01 = (const int*)d_in[8];
    const int* wc02 = (const int*)d_in[9];
    const int* wc10 = (const int*)d_in[10];
    const int* wc11 = (const int*)d_in[11];
    const int* wc12 = (const int*)d_in[12];

    pre_kernel<<<PREP_BLOCKS + BUILD_BLOCKS + 1, 256>>>(
        x, (float*)d_out, W1, b1, W2, b2,
        gi0, gi1, wc00, wc01, wc02, wc10, wc11, wc12);
    main_kernel<<<NCH, 64>>>((float*)d_out);
}